// round 15
// baseline (speedup 1.0000x reference)
#include <cuda_runtime.h>
#include <cuda_bf16.h>
#include <cstdint>

#define BATCH 4
#define SEQ 2048
#define DMODEL 1024
#define NHEADS 16
#define DK 64
#define MTOT (BATCH * SEQ)   // 8192

// softmax scale folded into Q projection: scale * log2(e)
#define CSCALE 0.18033688011112042f

// ---------------- scratch ----------------------------------------------------
__device__ __nv_bfloat16 g_xb[MTOT * DMODEL];
__device__ __nv_bfloat16 g_kb[MTOT * DMODEL];
__device__ __nv_bfloat16 g_vb[MTOT * DMODEL];
__device__ __nv_bfloat16 g_Wqb[DMODEL * DMODEL];
__device__ __nv_bfloat16 g_Wkb[DMODEL * DMODEL];
__device__ __nv_bfloat16 g_Wvb[DMODEL * DMODEL];
__device__ __nv_bfloat16 g_Wob[DMODEL * DMODEL];
__device__ __nv_bfloat16 g_Qb[BATCH * NHEADS * SEQ * DK];   // [B,H,S,DK], pre-scaled by CSCALE
__device__ __nv_bfloat16 g_Kb[BATCH * NHEADS * SEQ * DK];
__device__ __nv_bfloat16 g_Vb[BATCH * NHEADS * SEQ * DK];
__device__ __nv_bfloat16 g_ctxb[MTOT * DMODEL];
__device__ float g_proj[MTOT * DMODEL];

// ---------------- converts (fused, z-indexed) ---------------------------------
__global__ void __launch_bounds__(256)
f2b3_kernel(const float* __restrict__ q, const float* __restrict__ k,
            const float* __restrict__ v) {
    const int z = blockIdx.z;
    const float* src = (z == 0) ? q : (z == 1) ? k : v;
    __nv_bfloat16* dst = (z == 0) ? g_xb : (z == 1) ? g_kb : g_vb;
    int i = blockIdx.x * blockDim.x + threadIdx.x;
    float4 val = ((const float4*)src)[i];
    ((__nv_bfloat162*)dst)[2 * i]     = __float22bfloat162_rn(make_float2(val.x, val.y));
    ((__nv_bfloat162*)dst)[2 * i + 1] = __float22bfloat162_rn(make_float2(val.z, val.w));
}

__global__ void __launch_bounds__(256)
f2b4_kernel(const float* __restrict__ wq, const float* __restrict__ wk,
            const float* __restrict__ wv, const float* __restrict__ wo) {
    const int z = blockIdx.z;
    const float* src = (z == 0) ? wq : (z == 1) ? wk : (z == 2) ? wv : wo;
    __nv_bfloat16* dst = (z == 0) ? g_Wqb : (z == 1) ? g_Wkb : (z == 2) ? g_Wvb : g_Wob;
    int i = blockIdx.x * blockDim.x + threadIdx.x;
    float4 val = ((const float4*)src)[i];
    ((__nv_bfloat162*)dst)[2 * i]     = __float22bfloat162_rn(make_float2(val.x, val.y));
    ((__nv_bfloat162*)dst)[2 * i + 1] = __float22bfloat162_rn(make_float2(val.z, val.w));
}

// ---------------- PTX helpers -------------------------------------------------
__device__ __forceinline__ void cp_async16(void* smem_dst, const void* gmem_src) {
    unsigned int a = (unsigned int)__cvta_generic_to_shared(smem_dst);
    asm volatile("cp.async.cg.shared.global [%0], [%1], 16;\n" :: "r"(a), "l"(gmem_src));
}
#define CP_COMMIT() asm volatile("cp.async.commit_group;\n" ::: "memory")
#define CP_WAIT0()  asm volatile("cp.async.wait_group 0;\n" ::: "memory")
#define CP_WAIT1()  asm volatile("cp.async.wait_group 1;\n" ::: "memory")
#define CP_WAIT2()  asm volatile("cp.async.wait_group 2;\n" ::: "memory")

__device__ __forceinline__ unsigned int s2u(const void* p) {
    return (unsigned int)__cvta_generic_to_shared(p);
}
__device__ __forceinline__ void ldmx4(uint32_t& r0, uint32_t& r1, uint32_t& r2, uint32_t& r3,
                                      unsigned int a) {
    asm volatile("ldmatrix.sync.aligned.m8n8.x4.shared.b16 {%0,%1,%2,%3},[%4];"
                 : "=r"(r0), "=r"(r1), "=r"(r2), "=r"(r3) : "r"(a));
}
__device__ __forceinline__ void ldmx4t(uint32_t& r0, uint32_t& r1, uint32_t& r2, uint32_t& r3,
                                       unsigned int a) {
    asm volatile("ldmatrix.sync.aligned.m8n8.x4.trans.shared.b16 {%0,%1,%2,%3},[%4];"
                 : "=r"(r0), "=r"(r1), "=r"(r2), "=r"(r3) : "r"(a));
}
__device__ __forceinline__ void mma16816(float& d0, float& d1, float& d2, float& d3,
                                         uint32_t a0, uint32_t a1, uint32_t a2, uint32_t a3,
                                         uint32_t b0, uint32_t b1) {
    asm volatile(
        "mma.sync.aligned.m16n8k16.row.col.f32.bf16.bf16.f32 "
        "{%0,%1,%2,%3}, {%4,%5,%6,%7}, {%8,%9}, {%0,%1,%2,%3};"
        : "+f"(d0), "+f"(d1), "+f"(d2), "+f"(d3)
        : "r"(a0), "r"(a1), "r"(a2), "r"(a3), "r"(b0), "r"(b1));
}
__device__ __forceinline__ float fexp2(float x) {
    float y;
    asm("ex2.approx.ftz.f32 %0, %1;" : "=f"(y) : "f"(x));
    return y;
}
__device__ __forceinline__ uint32_t packbf(float a, float b) {
    __nv_bfloat162 t = __float22bfloat162_rn(make_float2(a, b));
    return *reinterpret_cast<uint32_t*>(&t);
}

// ---------------- bf16 GEMM core: 3-stage cp.async, warp tile 64x64 ------------
#define GBM 128
#define GBN 128
#define GBK 64
#define GLDA 72
#define GLDB 136
#define GA_BYTES (GBM * GLDA * 2)                        // 18432
#define GB_BYTES (GBK * GLDB * 2)                        // 17408
#define GEMM_SMEM (3 * (GA_BYTES + GB_BYTES))            // 107520 B
#define NKT (DMODEL / GBK)                               // 16

__device__ __forceinline__ void gemm_core(const __nv_bfloat16* __restrict__ A,
                                          const __nv_bfloat16* __restrict__ W,
                                          const float* __restrict__ bias, int out_sel) {
    extern __shared__ __align__(16) char smraw[];
    __nv_bfloat16* As[3] = { (__nv_bfloat16*)(smraw),
                             (__nv_bfloat16*)(smraw + GA_BYTES),
                             (__nv_bfloat16*)(smraw + 2 * GA_BYTES) };
    __nv_bfloat16* Bs[3] = { (__nv_bfloat16*)(smraw + 3 * GA_BYTES),
                             (__nv_bfloat16*)(smraw + 3 * GA_BYTES + GB_BYTES),
                             (__nv_bfloat16*)(smraw + 3 * GA_BYTES + 2 * GB_BYTES) };

    const int t = threadIdx.x;
    const int lane = t & 31;
    const int warp = t >> 5;
    const int wm = warp >> 1;
    const int wn = warp & 1;
    const int row0 = blockIdx.y * GBM;
    const int col0 = blockIdx.x * GBN;

    float d[4][8][4];
    {
        const int cb = col0 + wn * 64 + 2 * (lane & 3);
#pragma unroll
        for (int nf = 0; nf < 8; nf++) {
            float b0 = bias[cb + nf * 8];
            float b1 = bias[cb + nf * 8 + 1];
#pragma unroll
            for (int mf = 0; mf < 4; mf++) {
                d[mf][nf][0] = b0; d[mf][nf][1] = b1;
                d[mf][nf][2] = b0; d[mf][nf][3] = b1;
            }
        }
    }

    auto load_tile = [&](int kt, int b) {
        const int k0 = kt * GBK;
#pragma unroll
        for (int i = 0; i < 8; i++) {
            int idx = t + i * 128;
            int r = idx >> 3, v = idx & 7;
            cp_async16(As[b] + r * GLDA + v * 8, A + (size_t)(row0 + r) * DMODEL + k0 + v * 8);
        }
#pragma unroll
        for (int i = 0; i < 8; i++) {
            int idx = t + i * 128;
            int r = idx >> 4, v = idx & 15;
            cp_async16(Bs[b] + r * GLDB + v * 8, W + (size_t)(k0 + r) * DMODEL + col0 + v * 8);
        }
        CP_COMMIT();
    };

    load_tile(0, 0);
    load_tile(1, 1);
    load_tile(2, 2);

    const int lrow = lane & 15;
    const int lcol8 = (lane >> 4) << 3;

    int buf = 0;
    for (int kt = 0; kt < NKT; kt++) {
        if (kt < NKT - 2)      { CP_WAIT2(); }
        else if (kt == NKT - 2){ CP_WAIT1(); }
        else                   { CP_WAIT0(); }
        __syncthreads();

        const __nv_bfloat16* At = As[buf];
        const __nv_bfloat16* Bt = Bs[buf];
#pragma unroll
        for (int ks = 0; ks < GBK / 16; ks++) {
            uint32_t af[4][4];
#pragma unroll
            for (int mf = 0; mf < 4; mf++)
                ldmx4(af[mf][0], af[mf][1], af[mf][2], af[mf][3],
                      s2u(At + (wm * 64 + mf * 16 + lrow) * GLDA + ks * 16 + lcol8));
#pragma unroll
            for (int nf16 = 0; nf16 < 4; nf16++) {
                uint32_t b0, b1, b2, b3;
                ldmx4t(b0, b1, b2, b3,
                       s2u(Bt + (ks * 16 + lrow) * GLDB + wn * 64 + nf16 * 16 + lcol8));
#pragma unroll
                for (int mf = 0; mf < 4; mf++) {
                    mma16816(d[mf][2 * nf16][0], d[mf][2 * nf16][1],
                             d[mf][2 * nf16][2], d[mf][2 * nf16][3],
                             af[mf][0], af[mf][1], af[mf][2], af[mf][3], b0, b1);
                    mma16816(d[mf][2 * nf16 + 1][0], d[mf][2 * nf16 + 1][1],
                             d[mf][2 * nf16 + 1][2], d[mf][2 * nf16 + 1][3],
                             af[mf][0], af[mf][1], af[mf][2], af[mf][3], b2, b3);
                }
            }
        }
        __syncthreads();
        if (kt + 3 < NKT) load_tile(kt + 3, buf);
        buf = (buf == 2) ? 0 : buf + 1;
    }

    // epilogue (Q output pre-scaled by CSCALE for the folded softmax scale)
    const float osc = (out_sel == 0) ? CSCALE : 1.f;
    const int rbase = row0 + wm * 64 + (lane >> 2);
    const int cb2 = wn * 64 + 2 * (lane & 3);
    if (out_sel <= 2) {
        __nv_bfloat16* outb = (out_sel == 0) ? g_Qb : (out_sel == 1) ? g_Kb : g_Vb;
#pragma unroll
        for (int mf = 0; mf < 4; mf++) {
#pragma unroll
            for (int half = 0; half < 2; half++) {
                int gr = rbase + mf * 16 + half * 8;
                int b = gr >> 11, s0 = gr & (SEQ - 1);
#pragma unroll
                for (int nf = 0; nf < 8; nf++) {
                    int gc = col0 + cb2 + nf * 8;
                    int h = gc >> 6, d0 = gc & (DK - 1);
                    *(__nv_bfloat162*)(outb + ((size_t)(b * NHEADS + h) * SEQ + s0) * DK + d0) =
                        __float22bfloat162_rn(
                            make_float2(d[mf][nf][2 * half] * osc,
                                        d[mf][nf][2 * half + 1] * osc));
                }
            }
        }
    } else {
#pragma unroll
        for (int mf = 0; mf < 4; mf++) {
#pragma unroll
            for (int half = 0; half < 2; half++) {
                int gr = rbase + mf * 16 + half * 8;
#pragma unroll
                for (int nf = 0; nf < 8; nf++) {
                    int gc = col0 + cb2 + nf * 8;
                    *(float2*)(g_proj + (size_t)gr * DMODEL + gc) =
                        make_float2(d[mf][nf][2 * half], d[mf][nf][2 * half + 1]);
                }
            }
        }
    }
}

__global__ void __launch_bounds__(128, 2)
gemm_qkv(const float* __restrict__ bq, const float* __restrict__ bk,
         const float* __restrict__ bv) {
    const int z = blockIdx.z;
    const __nv_bfloat16* A = (z == 0) ? g_xb  : (z == 1) ? g_kb  : g_vb;
    const __nv_bfloat16* W = (z == 0) ? g_Wqb : (z == 1) ? g_Wkb : g_Wvb;
    const float* bias      = (z == 0) ? bq    : (z == 1) ? bk    : bv;
    gemm_core(A, W, bias, z);
}

__global__ void __launch_bounds__(128, 2)
gemm_o(const float* __restrict__ bo) {
    gemm_core(g_ctxb, g_Wob, bo, 3);
}

// ---------------- Flash attention v4: scale pre-folded into Q -----------------
#define AQT 128
#define AKT 64
#define AALD 72
#define ATTN_SMEM ((AQT * AALD + 4 * AKT * AALD) * 2)   // 55296 B

__global__ void __launch_bounds__(256, 2)
attn_kernel() {
    extern __shared__ __align__(16) char smraw[];
    __nv_bfloat16* Qs = (__nv_bfloat16*)smraw;
    __nv_bfloat16* Ks0 = Qs + AQT * AALD;
    __nv_bfloat16* Vs0 = Ks0 + 2 * AKT * AALD;
    __nv_bfloat16* Ksb[2] = { Ks0, Ks0 + AKT * AALD };
    __nv_bfloat16* Vsb[2] = { Vs0, Vs0 + AKT * AALD };

    const int t = threadIdx.x;
    const int lane = t & 31;
    const int warp = t >> 5;
    const int q0 = blockIdx.x * AQT;
    const int bh = blockIdx.y;
    const __nv_bfloat16* Qg = g_Qb + (size_t)bh * SEQ * DK;
    const __nv_bfloat16* Kg = g_Kb + (size_t)bh * SEQ * DK;
    const __nv_bfloat16* Vg = g_Vb + (size_t)bh * SEQ * DK;

#pragma unroll
    for (int i = 0; i < 2; i++) {
        int idx = t + i * 256;
        int r = idx >> 3, v = idx & 7;
        cp_async16(Ksb[0] + r * AALD + v * 8, Kg + (size_t)r * DK + v * 8);
        cp_async16(Vsb[0] + r * AALD + v * 8, Vg + (size_t)r * DK + v * 8);
    }
    CP_COMMIT();

#pragma unroll
    for (int i = 0; i < 4; i++) {
        int idx = t + i * 256;
        int r = idx >> 3, v = idx & 7;
        *(uint4*)(Qs + r * AALD + v * 8) = *(const uint4*)(Qg + (size_t)(q0 + r) * DK + v * 8);
    }
    __syncthreads();

    uint32_t qa[4][4];
    {
        int row = warp * 16 + (lane & 15);
        int col8 = (lane >> 4) << 3;
#pragma unroll
        for (int ks = 0; ks < 4; ks++)
            ldmx4(qa[ks][0], qa[ks][1], qa[ks][2], qa[ks][3],
                  s2u(Qs + row * AALD + ks * 16 + col8));
    }

    float ofr[8][4];
#pragma unroll
    for (int f = 0; f < 8; f++)
#pragma unroll
        for (int e = 0; e < 4; e++) ofr[f][e] = 0.f;
    float mt0 = -1e30f, mt1 = -1e30f, l0 = 0.f, l1 = 0.f;

    const int NTILE = SEQ / AKT;
    for (int kt = 0; kt < NTILE; kt++) {
        const int buf = kt & 1;
        CP_WAIT0();
        __syncthreads();
        if (kt + 1 < NTILE) {
            const __nv_bfloat16* Kn = Kg + (size_t)(kt + 1) * AKT * DK;
            const __nv_bfloat16* Vn = Vg + (size_t)(kt + 1) * AKT * DK;
#pragma unroll
            for (int i = 0; i < 2; i++) {
                int idx = t + i * 256;
                int r = idx >> 3, v = idx & 7;
                cp_async16(Ksb[buf ^ 1] + r * AALD + v * 8, Kn + (size_t)r * DK + v * 8);
                cp_async16(Vsb[buf ^ 1] + r * AALD + v * 8, Vn + (size_t)r * DK + v * 8);
            }
            CP_COMMIT();
        }

        float sfr[8][4];
#pragma unroll
        for (int f = 0; f < 8; f++)
#pragma unroll
            for (int e = 0; e < 4; e++) sfr[f][e] = 0.f;

        {
            const __nv_bfloat16* Kt = Ksb[buf];
            int krow = (lane & 15);
            int kc8 = (lane >> 4) << 3;
#pragma unroll
            for (int ks = 0; ks < 4; ks++) {
#pragma unroll
                for (int fb = 0; fb < 4; fb++) {
                    uint32_t k0, k1, k2, k3;
                    ldmx4(k0, k1, k2, k3,
                          s2u(Kt + (fb * 16 + krow) * AALD + ks * 16 + kc8));
                    mma16816(sfr[2 * fb][0], sfr[2 * fb][1], sfr[2 * fb][2], sfr[2 * fb][3],
                             qa[ks][0], qa[ks][1], qa[ks][2], qa[ks][3], k0, k2);
                    mma16816(sfr[2 * fb + 1][0], sfr[2 * fb + 1][1], sfr[2 * fb + 1][2], sfr[2 * fb + 1][3],
                             qa[ks][0], qa[ks][1], qa[ks][2], qa[ks][3], k1, k3);
                }
            }
        }

        // scores already in log2 domain (Q pre-scaled): softmax directly
        float mx0 = -1e30f, mx1 = -1e30f;
#pragma unroll
        for (int f = 0; f < 8; f++) {
            mx0 = fmaxf(mx0, fmaxf(sfr[f][0], sfr[f][1]));
            mx1 = fmaxf(mx1, fmaxf(sfr[f][2], sfr[f][3]));
        }
        mx0 = fmaxf(mx0, __shfl_xor_sync(0xffffffffu, mx0, 1));
        mx0 = fmaxf(mx0, __shfl_xor_sync(0xffffffffu, mx0, 2));
        mx1 = fmaxf(mx1, __shfl_xor_sync(0xffffffffu, mx1, 1));
        mx1 = fmaxf(mx1, __shfl_xor_sync(0xffffffffu, mx1, 2));
        float m0n = fmaxf(mt0, mx0), m1n = fmaxf(mt1, mx1);
        float al0 = fexp2(mt0 - m0n), al1 = fexp2(mt1 - m1n);
        mt0 = m0n; mt1 = m1n;

        float ps0 = 0.f, ps1 = 0.f;
#pragma unroll
        for (int f = 0; f < 8; f++) {
            sfr[f][0] = fexp2(sfr[f][0] - m0n);
            sfr[f][1] = fexp2(sfr[f][1] - m0n);
            sfr[f][2] = fexp2(sfr[f][2] - m1n);
            sfr[f][3] = fexp2(sfr[f][3] - m1n);
            ps0 += sfr[f][0] + sfr[f][1];
            ps1 += sfr[f][2] + sfr[f][3];
        }
        l0 = l0 * al0 + ps0;
        l1 = l1 * al1 + ps1;

#pragma unroll
        for (int f = 0; f < 8; f++) {
            ofr[f][0] *= al0; ofr[f][1] *= al0;
            ofr[f][2] *= al1; ofr[f][3] *= al1;
        }

        {
            const __nv_bfloat16* Vt = Vsb[buf];
            int vrow = (lane & 15);
            int vc8 = (lane >> 4) << 3;
#pragma unroll
            for (int ks = 0; ks < 4; ks++) {
                uint32_t a0 = packbf(sfr[2 * ks][0],     sfr[2 * ks][1]);
                uint32_t a1 = packbf(sfr[2 * ks][2],     sfr[2 * ks][3]);
                uint32_t a2 = packbf(sfr[2 * ks + 1][0], sfr[2 * ks + 1][1]);
                uint32_t a3 = packbf(sfr[2 * ks + 1][2], sfr[2 * ks + 1][3]);
#pragma unroll
                for (int fp = 0; fp < 4; fp++) {
                    uint32_t v0, v1, v2, v3;
                    ldmx4t(v0, v1, v2, v3,
                           s2u(Vt + (ks * 16 + vrow) * AALD + fp * 16 + vc8));
                    mma16816(ofr[2 * fp][0], ofr[2 * fp][1], ofr[2 * fp][2], ofr[2 * fp][3],
                             a0, a1, a2, a3, v0, v1);
                    mma16816(ofr[2 * fp + 1][0], ofr[2 * fp + 1][1], ofr[2 * fp + 1][2], ofr[2 * fp + 1][3],
                             a0, a1, a2, a3, v2, v3);
                }
            }
        }
    }

    l0 += __shfl_xor_sync(0xffffffffu, l0, 1);
    l0 += __shfl_xor_sync(0xffffffffu, l0, 2);
    l1 += __shfl_xor_sync(0xffffffffu, l1, 1);
    l1 += __shfl_xor_sync(0xffffffffu, l1, 2);
    float inv0 = 1.f / l0, inv1 = 1.f / l1;

    const int b = bh >> 4, h = bh & 15;
    int row0 = q0 + warp * 16 + (lane >> 2);
    int colb = h * DK + 2 * (lane & 3);
#pragma unroll
    for (int f = 0; f < 8; f++) {
        *(__nv_bfloat162*)(g_ctxb + (size_t)(b * SEQ + row0) * DMODEL + colb + f * 8) =
            __float22bfloat162_rn(make_float2(ofr[f][0] * inv0, ofr[f][1] * inv0));
        *(__nv_bfloat162*)(g_ctxb + (size_t)(b * SEQ + row0 + 8) * DMODEL + colb + f * 8) =
            __float22bfloat162_rn(make_float2(ofr[f][2] * inv1, ofr[f][3] * inv1));
    }
}

// ---------------- residual + LayerNorm ---------------------------------------
__global__ void __launch_bounds__(256)
ln_kernel(const float* __restrict__ residual, const float* __restrict__ gamma,
          const float* __restrict__ beta, float* __restrict__ out) {
    const int row = blockIdx.x;
    const int t = threadIdx.x;
    const size_t base = (size_t)row * DMODEL + t * 4;

    float4 r4 = *(const float4*)(residual + base);
    float4 p4 = *(const float4*)(g_proj + base);
    float x0 = r4.x + p4.x, x1 = r4.y + p4.y, x2 = r4.z + p4.z, x3 = r4.w + p4.w;

    float s = x0 + x1 + x2 + x3;
    float ss = x0 * x0 + x1 * x1 + x2 * x2 + x3 * x3;
#pragma unroll
    for (int off = 16; off > 0; off >>= 1) {
        s += __shfl_xor_sync(0xffffffffu, s, off);
        ss += __shfl_xor_sync(0xffffffffu, ss, off);
    }
    __shared__ float rs[8], rss[8], stat[2];
    int w = t >> 5, lane = t & 31;
    if (lane == 0) { rs[w] = s; rss[w] = ss; }
    __syncthreads();
    if (t == 0) {
        float S = 0.f, SS = 0.f;
#pragma unroll
        for (int i = 0; i < 8; i++) { S += rs[i]; SS += rss[i]; }
        float mean = S * (1.f / DMODEL);
        float var = SS * (1.f / DMODEL) - mean * mean;
        stat[0] = mean;
        stat[1] = rsqrtf(var + 1e-5f);
    }
    __syncthreads();
    float mean = stat[0], inv = stat[1];

    float4 g4 = *(const float4*)(gamma + t * 4);
    float4 b4 = *(const float4*)(beta + t * 4);
    float4 y;
    y.x = (x0 - mean) * inv * g4.x + b4.x;
    y.y = (x1 - mean) * inv * g4.y + b4.y;
    y.z = (x2 - mean) * inv * g4.z + b4.z;
    y.w = (x3 - mean) * inv * g4.w + b4.w;
    *(float4*)(out + base) = y;
}

// ---------------- launch ------------------------------------------------------
extern "C" void kernel_launch(void* const* d_in, const int* in_sizes, int n_in,
                              void* d_out, int out_size) {
    const float* query = (const float*)d_in[0];
    const float* key   = (const float*)d_in[1];
    const float* value = (const float*)d_in[2];
    const float* Wq    = (const float*)d_in[3];
    const float* bq    = (const float*)d_in[4];
    const float* Wk    = (const float*)d_in[5];
    const float* bk    = (const float*)d_in[6];
    const float* Wv    = (const float*)d_in[7];
    const float* bv    = (const float*)d_in[8];
    const float* Wo    = (const float*)d_in[9];
    const float* bo    = (const float*)d_in[10];
    const float* gamma = (const float*)d_in[11];
    const float* beta  = (const float*)d_in[12];
    float* out = (float*)d_out;

    static bool attr_done = false;
    if (!attr_done) {
        (void)cudaFuncSetAttribute(gemm_qkv,
                                   cudaFuncAttributeMaxDynamicSharedMemorySize, GEMM_SMEM);
        (void)cudaFuncSetAttribute(gemm_o,
                                   cudaFuncAttributeMaxDynamicSharedMemorySize, GEMM_SMEM);
        (void)cudaFuncSetAttribute(attn_kernel,
                                   cudaFuncAttributeMaxDynamicSharedMemorySize, ATTN_SMEM);
        attr_done = true;
    }

    const int n4_act = MTOT * DMODEL / 4;     // 2097152
    const int n4_w   = DMODEL * DMODEL / 4;   // 262144
    dim3 cgrid3(n4_act / 256, 1, 3);
    dim3 cgrid4(n4_w / 256, 1, 4);
    f2b3_kernel<<<cgrid3, 256>>>(query, key, value);
    f2b4_kernel<<<cgrid4, 256>>>(Wq, Wk, Wv, Wo);

    dim3 gq(DMODEL / GBN, MTOT / GBM, 3);   // (8, 64, 3)
    gemm_qkv<<<gq, 128, GEMM_SMEM>>>(bq, bk, bv);

    dim3 agrid(SEQ / AQT, BATCH * NHEADS);  // (16, 64)
    attn_kernel<<<agrid, 256, ATTN_SMEM>>>();

    dim3 go(DMODEL / GBN, MTOT / GBM);      // (8, 64)
    gemm_o<<<go, 128, GEMM_SMEM>>>(bo);

    ln_kernel<<<MTOT, 256>>>(query, gamma, beta, out);
}

// round 16
// speedup vs baseline: 1.0335x; 1.0335x over previous
#include <cuda_runtime.h>
#include <cuda_bf16.h>
#include <cstdint>

#define BATCH 4
#define SEQ 2048
#define DMODEL 1024
#define NHEADS 16
#define DK 64
#define MTOT (BATCH * SEQ)   // 8192

// softmax scale folded into Q projection: 0.125 * log2(e)
#define CSCALE 0.18033688011112042f

// ---------------- scratch ----------------------------------------------------
__device__ __nv_bfloat16 g_xb[MTOT * DMODEL];
__device__ __nv_bfloat16 g_kb[MTOT * DMODEL];
__device__ __nv_bfloat16 g_vb[MTOT * DMODEL];
__device__ __nv_bfloat16 g_Wqb[DMODEL * DMODEL];
__device__ __nv_bfloat16 g_Wkb[DMODEL * DMODEL];
__device__ __nv_bfloat16 g_Wvb[DMODEL * DMODEL];
__device__ __nv_bfloat16 g_Wob[DMODEL * DMODEL];
__device__ __nv_bfloat16 g_Qb[BATCH * NHEADS * SEQ * DK];   // pre-scaled by CSCALE
__device__ __nv_bfloat16 g_Kb[BATCH * NHEADS * SEQ * DK];
__device__ __nv_bfloat16 g_Vb[BATCH * NHEADS * SEQ * DK];
__device__ __nv_bfloat16 g_ctxb[MTOT * DMODEL];
__device__ float g_proj[MTOT * DMODEL];

// ---------------- fused converts (single launch, 7 regions) -------------------
#define A4 (MTOT * DMODEL / 4)      // 2097152 float4 per activation
#define W4 (DMODEL * DMODEL / 4)    // 262144 float4 per weight
#define CONV_TOTAL (3 * A4 + 4 * W4)

__global__ void __launch_bounds__(256)
f2b_all(const float* __restrict__ q, const float* __restrict__ k,
        const float* __restrict__ v, const float* __restrict__ wq,
        const float* __restrict__ wk, const float* __restrict__ wv,
        const float* __restrict__ wo) {
    int i = blockIdx.x * 256 + threadIdx.x;
    if (i >= CONV_TOTAL) return;
    const float* src;
    __nv_bfloat16* dst;
    int off;
    if (i < 3 * A4) {
        int z = i >> 21;            // / A4
        off = i & (A4 - 1);
        src = (z == 0) ? q : (z == 1) ? k : v;
        dst = (z == 0) ? g_xb : (z == 1) ? g_kb : g_vb;
    } else {
        int j = i - 3 * A4;
        int z = j >> 18;            // / W4
        off = j & (W4 - 1);
        src = (z == 0) ? wq : (z == 1) ? wk : (z == 2) ? wv : wo;
        dst = (z == 0) ? g_Wqb : (z == 1) ? g_Wkb : (z == 2) ? g_Wvb : g_Wob;
    }
    float4 val = ((const float4*)src)[off];
    ((__nv_bfloat162*)dst)[2 * off]     = __float22bfloat162_rn(make_float2(val.x, val.y));
    ((__nv_bfloat162*)dst)[2 * off + 1] = __float22bfloat162_rn(make_float2(val.z, val.w));
}

// ---------------- PTX helpers -------------------------------------------------
__device__ __forceinline__ void cp_async16(void* smem_dst, const void* gmem_src) {
    unsigned int a = (unsigned int)__cvta_generic_to_shared(smem_dst);
    asm volatile("cp.async.cg.shared.global [%0], [%1], 16;\n" :: "r"(a), "l"(gmem_src));
}
#define CP_COMMIT() asm volatile("cp.async.commit_group;\n" ::: "memory")
#define CP_WAIT0()  asm volatile("cp.async.wait_group 0;\n" ::: "memory")

__device__ __forceinline__ unsigned int s2u(const void* p) {
    return (unsigned int)__cvta_generic_to_shared(p);
}
__device__ __forceinline__ void ldmx4(uint32_t& r0, uint32_t& r1, uint32_t& r2, uint32_t& r3,
                                      unsigned int a) {
    asm volatile("ldmatrix.sync.aligned.m8n8.x4.shared.b16 {%0,%1,%2,%3},[%4];"
                 : "=r"(r0), "=r"(r1), "=r"(r2), "=r"(r3) : "r"(a));
}
__device__ __forceinline__ void ldmx4t(uint32_t& r0, uint32_t& r1, uint32_t& r2, uint32_t& r3,
                                       unsigned int a) {
    asm volatile("ldmatrix.sync.aligned.m8n8.x4.trans.shared.b16 {%0,%1,%2,%3},[%4];"
                 : "=r"(r0), "=r"(r1), "=r"(r2), "=r"(r3) : "r"(a));
}
__device__ __forceinline__ void mma16816(float& d0, float& d1, float& d2, float& d3,
                                         uint32_t a0, uint32_t a1, uint32_t a2, uint32_t a3,
                                         uint32_t b0, uint32_t b1) {
    asm volatile(
        "mma.sync.aligned.m16n8k16.row.col.f32.bf16.bf16.f32 "
        "{%0,%1,%2,%3}, {%4,%5,%6,%7}, {%8,%9}, {%0,%1,%2,%3};"
        : "+f"(d0), "+f"(d1), "+f"(d2), "+f"(d3)
        : "r"(a0), "r"(a1), "r"(a2), "r"(a3), "r"(b0), "r"(b1));
}
__device__ __forceinline__ float fexp2(float x) {
    float y;
    asm("ex2.approx.ftz.f32 %0, %1;" : "=f"(y) : "f"(x));
    return y;
}
__device__ __forceinline__ uint32_t packbf(float a, float b) {
    __nv_bfloat162 t = __float22bfloat162_rn(make_float2(a, b));
    return *reinterpret_cast<uint32_t*>(&t);
}

// ---------------- bf16 GEMM core: 2-stage cp.async, warp tile 64x64 ------------
#define GBM 128
#define GBN 128
#define GBK 64
#define GLDA 72
#define GLDB 136
#define GEMM_SMEM (2 * (GBM * GLDA + GBK * GLDB) * 2)   // 71680 B
#define NKT (DMODEL / GBK)                              // 16

__device__ __forceinline__ void gemm_core(const __nv_bfloat16* __restrict__ A,
                                          const __nv_bfloat16* __restrict__ W,
                                          const float* __restrict__ bias, int out_sel) {
    extern __shared__ __align__(16) char smraw[];
    __nv_bfloat16* As[2] = { (__nv_bfloat16*)smraw,
                             (__nv_bfloat16*)smraw + GBM * GLDA };
    __nv_bfloat16* Bs[2] = { (__nv_bfloat16*)smraw + 2 * GBM * GLDA,
                             (__nv_bfloat16*)smraw + 2 * GBM * GLDA + GBK * GLDB };

    const int t = threadIdx.x;
    const int lane = t & 31;
    const int warp = t >> 5;
    const int wm = warp >> 1;
    const int wn = warp & 1;
    const int row0 = blockIdx.y * GBM;
    const int col0 = blockIdx.x * GBN;

    float d[4][8][4];
    {
        const int cb = col0 + wn * 64 + 2 * (lane & 3);
#pragma unroll
        for (int nf = 0; nf < 8; nf++) {
            float b0 = bias[cb + nf * 8];
            float b1 = bias[cb + nf * 8 + 1];
#pragma unroll
            for (int mf = 0; mf < 4; mf++) {
                d[mf][nf][0] = b0; d[mf][nf][1] = b1;
                d[mf][nf][2] = b0; d[mf][nf][3] = b1;
            }
        }
    }

    {
#pragma unroll
        for (int i = 0; i < 8; i++) {
            int idx = t + i * 128;
            int r = idx >> 3, v = idx & 7;
            cp_async16(As[0] + r * GLDA + v * 8, A + (size_t)(row0 + r) * DMODEL + v * 8);
        }
#pragma unroll
        for (int i = 0; i < 8; i++) {
            int idx = t + i * 128;
            int r = idx >> 4, v = idx & 15;
            cp_async16(Bs[0] + r * GLDB + v * 8, W + (size_t)r * DMODEL + col0 + v * 8);
        }
        CP_COMMIT();
    }

    const int lrow = lane & 15;
    const int lcol8 = (lane >> 4) << 3;

    for (int kt = 0; kt < NKT; kt++) {
        const int buf = kt & 1;
        CP_WAIT0();
        __syncthreads();
        if (kt + 1 < NKT) {
            const int k1 = (kt + 1) * GBK;
#pragma unroll
            for (int i = 0; i < 8; i++) {
                int idx = t + i * 128;
                int r = idx >> 3, v = idx & 7;
                cp_async16(As[buf ^ 1] + r * GLDA + v * 8,
                           A + (size_t)(row0 + r) * DMODEL + k1 + v * 8);
            }
#pragma unroll
            for (int i = 0; i < 8; i++) {
                int idx = t + i * 128;
                int r = idx >> 4, v = idx & 15;
                cp_async16(Bs[buf ^ 1] + r * GLDB + v * 8,
                           W + (size_t)(k1 + r) * DMODEL + col0 + v * 8);
            }
            CP_COMMIT();
        }

        const __nv_bfloat16* At = As[buf];
        const __nv_bfloat16* Bt = Bs[buf];
#pragma unroll
        for (int ks = 0; ks < GBK / 16; ks++) {
            uint32_t af[4][4];
#pragma unroll
            for (int mf = 0; mf < 4; mf++)
                ldmx4(af[mf][0], af[mf][1], af[mf][2], af[mf][3],
                      s2u(At + (wm * 64 + mf * 16 + lrow) * GLDA + ks * 16 + lcol8));
#pragma unroll
            for (int nf16 = 0; nf16 < 4; nf16++) {
                uint32_t b0, b1, b2, b3;
                ldmx4t(b0, b1, b2, b3,
                       s2u(Bt + (ks * 16 + lrow) * GLDB + wn * 64 + nf16 * 16 + lcol8));
#pragma unroll
                for (int mf = 0; mf < 4; mf++) {
                    mma16816(d[mf][2 * nf16][0], d[mf][2 * nf16][1],
                             d[mf][2 * nf16][2], d[mf][2 * nf16][3],
                             af[mf][0], af[mf][1], af[mf][2], af[mf][3], b0, b1);
                    mma16816(d[mf][2 * nf16 + 1][0], d[mf][2 * nf16 + 1][1],
                             d[mf][2 * nf16 + 1][2], d[mf][2 * nf16 + 1][3],
                             af[mf][0], af[mf][1], af[mf][2], af[mf][3], b2, b3);
                }
            }
        }
        __syncthreads();
    }

    // epilogue (Q output pre-scaled by CSCALE for the folded softmax scale)
    const float osc = (out_sel == 0) ? CSCALE : 1.f;
    const int rbase = row0 + wm * 64 + (lane >> 2);
    const int cb2 = wn * 64 + 2 * (lane & 3);
    if (out_sel <= 2) {
        __nv_bfloat16* outb = (out_sel == 0) ? g_Qb : (out_sel == 1) ? g_Kb : g_Vb;
#pragma unroll
        for (int mf = 0; mf < 4; mf++) {
#pragma unroll
            for (int half = 0; half < 2; half++) {
                int gr = rbase + mf * 16 + half * 8;
                int b = gr >> 11, s0 = gr & (SEQ - 1);
#pragma unroll
                for (int nf = 0; nf < 8; nf++) {
                    int gc = col0 + cb2 + nf * 8;
                    int h = gc >> 6, d0 = gc & (DK - 1);
                    *(__nv_bfloat162*)(outb + ((size_t)(b * NHEADS + h) * SEQ + s0) * DK + d0) =
                        __float22bfloat162_rn(
                            make_float2(d[mf][nf][2 * half] * osc,
                                        d[mf][nf][2 * half + 1] * osc));
                }
            }
        }
    } else {
#pragma unroll
        for (int mf = 0; mf < 4; mf++) {
#pragma unroll
            for (int half = 0; half < 2; half++) {
                int gr = rbase + mf * 16 + half * 8;
#pragma unroll
                for (int nf = 0; nf < 8; nf++) {
                    int gc = col0 + cb2 + nf * 8;
                    *(float2*)(g_proj + (size_t)gr * DMODEL + gc) =
                        make_float2(d[mf][nf][2 * half], d[mf][nf][2 * half + 1]);
                }
            }
        }
    }
}

__global__ void __launch_bounds__(128, 2)
gemm_qkv(const float* __restrict__ bq, const float* __restrict__ bk,
         const float* __restrict__ bv) {
    const int z = blockIdx.z;
    const __nv_bfloat16* A = (z == 0) ? g_xb  : (z == 1) ? g_kb  : g_vb;
    const __nv_bfloat16* W = (z == 0) ? g_Wqb : (z == 1) ? g_Wkb : g_Wvb;
    const float* bias      = (z == 0) ? bq    : (z == 1) ? bk    : bv;
    gemm_core(A, W, bias, z);
}

__global__ void __launch_bounds__(128, 2)
gemm_o(const float* __restrict__ bo) {
    gemm_core(g_ctxb, g_Wob, bo, 3);
}

// ---------------- Flash attention v4: scale pre-folded into Q -----------------
#define AQT 128
#define AKT 64
#define AALD 72
#define ATTN_SMEM ((AQT * AALD + 4 * AKT * AALD) * 2)   // 55296 B

__global__ void __launch_bounds__(256, 2)
attn_kernel() {
    extern __shared__ __align__(16) char smraw[];
    __nv_bfloat16* Qs = (__nv_bfloat16*)smraw;
    __nv_bfloat16* Ks0 = Qs + AQT * AALD;
    __nv_bfloat16* Vs0 = Ks0 + 2 * AKT * AALD;
    __nv_bfloat16* Ksb[2] = { Ks0, Ks0 + AKT * AALD };
    __nv_bfloat16* Vsb[2] = { Vs0, Vs0 + AKT * AALD };

    const int t = threadIdx.x;
    const int lane = t & 31;
    const int warp = t >> 5;
    const int q0 = blockIdx.x * AQT;
    const int bh = blockIdx.y;
    const __nv_bfloat16* Qg = g_Qb + (size_t)bh * SEQ * DK;
    const __nv_bfloat16* Kg = g_Kb + (size_t)bh * SEQ * DK;
    const __nv_bfloat16* Vg = g_Vb + (size_t)bh * SEQ * DK;

#pragma unroll
    for (int i = 0; i < 2; i++) {
        int idx = t + i * 256;
        int r = idx >> 3, v = idx & 7;
        cp_async16(Ksb[0] + r * AALD + v * 8, Kg + (size_t)r * DK + v * 8);
        cp_async16(Vsb[0] + r * AALD + v * 8, Vg + (size_t)r * DK + v * 8);
    }
    CP_COMMIT();

#pragma unroll
    for (int i = 0; i < 4; i++) {
        int idx = t + i * 256;
        int r = idx >> 3, v = idx & 7;
        *(uint4*)(Qs + r * AALD + v * 8) = *(const uint4*)(Qg + (size_t)(q0 + r) * DK + v * 8);
    }
    __syncthreads();

    uint32_t qa[4][4];
    {
        int row = warp * 16 + (lane & 15);
        int col8 = (lane >> 4) << 3;
#pragma unroll
        for (int ks = 0; ks < 4; ks++)
            ldmx4(qa[ks][0], qa[ks][1], qa[ks][2], qa[ks][3],
                  s2u(Qs + row * AALD + ks * 16 + col8));
    }

    float ofr[8][4];
#pragma unroll
    for (int f = 0; f < 8; f++)
#pragma unroll
        for (int e = 0; e < 4; e++) ofr[f][e] = 0.f;
    float mt0 = -1e30f, mt1 = -1e30f, l0 = 0.f, l1 = 0.f;

    const int NTILE = SEQ / AKT;
    for (int kt = 0; kt < NTILE; kt++) {
        const int buf = kt & 1;
        CP_WAIT0();
        __syncthreads();
        if (kt + 1 < NTILE) {
            const __nv_bfloat16* Kn = Kg + (size_t)(kt + 1) * AKT * DK;
            const __nv_bfloat16* Vn = Vg + (size_t)(kt + 1) * AKT * DK;
#pragma unroll
            for (int i = 0; i < 2; i++) {
                int idx = t + i * 256;
                int r = idx >> 3, v = idx & 7;
                cp_async16(Ksb[buf ^ 1] + r * AALD + v * 8, Kn + (size_t)r * DK + v * 8);
                cp_async16(Vsb[buf ^ 1] + r * AALD + v * 8, Vn + (size_t)r * DK + v * 8);
            }
            CP_COMMIT();
        }

        float sfr[8][4];
#pragma unroll
        for (int f = 0; f < 8; f++)
#pragma unroll
            for (int e = 0; e < 4; e++) sfr[f][e] = 0.f;

        {
            const __nv_bfloat16* Kt = Ksb[buf];
            int krow = (lane & 15);
            int kc8 = (lane >> 4) << 3;
#pragma unroll
            for (int ks = 0; ks < 4; ks++) {
#pragma unroll
                for (int fb = 0; fb < 4; fb++) {
                    uint32_t k0, k1, k2, k3;
                    ldmx4(k0, k1, k2, k3,
                          s2u(Kt + (fb * 16 + krow) * AALD + ks * 16 + kc8));
                    mma16816(sfr[2 * fb][0], sfr[2 * fb][1], sfr[2 * fb][2], sfr[2 * fb][3],
                             qa[ks][0], qa[ks][1], qa[ks][2], qa[ks][3], k0, k2);
                    mma16816(sfr[2 * fb + 1][0], sfr[2 * fb + 1][1], sfr[2 * fb + 1][2], sfr[2 * fb + 1][3],
                             qa[ks][0], qa[ks][1], qa[ks][2], qa[ks][3], k1, k3);
                }
            }
        }

        // scores already include the log2-domain scale (Q pre-scaled)
        float mx0 = -1e30f, mx1 = -1e30f;
#pragma unroll
        for (int f = 0; f < 8; f++) {
            mx0 = fmaxf(mx0, fmaxf(sfr[f][0], sfr[f][1]));
            mx1 = fmaxf(mx1, fmaxf(sfr[f][2], sfr[f][3]));
        }
        mx0 = fmaxf(mx0, __shfl_xor_sync(0xffffffffu, mx0, 1));
        mx0 = fmaxf(mx0, __shfl_xor_sync(0xffffffffu, mx0, 2));
        mx1 = fmaxf(mx1, __shfl_xor_sync(0xffffffffu, mx1, 1));
        mx1 = fmaxf(mx1, __shfl_xor_sync(0xffffffffu, mx1, 2));
        float m0n = fmaxf(mt0, mx0), m1n = fmaxf(mt1, mx1);
        float al0 = fexp2(mt0 - m0n), al1 = fexp2(mt1 - m1n);
        mt0 = m0n; mt1 = m1n;

        float ps0 = 0.f, ps1 = 0.f;
#pragma unroll
        for (int f = 0; f < 8; f++) {
            sfr[f][0] = fexp2(sfr[f][0] - m0n);
            sfr[f][1] = fexp2(sfr[f][1] - m0n);
            sfr[f][2] = fexp2(sfr[f][2] - m1n);
            sfr[f][3] = fexp2(sfr[f][3] - m1n);
            ps0 += sfr[f][0] + sfr[f][1];
            ps1 += sfr[f][2] + sfr[f][3];
        }
        l0 = l0 * al0 + ps0;
        l1 = l1 * al1 + ps1;

#pragma unroll
        for (int f = 0; f < 8; f++) {
            ofr[f][0] *= al0; ofr[f][1] *= al0;
            ofr[f][2] *= al1; ofr[f][3] *= al1;
        }

        {
            const __nv_bfloat16* Vt = Vsb[buf];
            int vrow = (lane & 15);
            int vc8 = (lane >> 4) << 3;
#pragma unroll
            for (int ks = 0; ks < 4; ks++) {
                uint32_t a0 = packbf(sfr[2 * ks][0],     sfr[2 * ks][1]);
                uint32_t a1 = packbf(sfr[2 * ks][2],     sfr[2 * ks][3]);
                uint32_t a2 = packbf(sfr[2 * ks + 1][0], sfr[2 * ks + 1][1]);
                uint32_t a3 = packbf(sfr[2 * ks + 1][2], sfr[2 * ks + 1][3]);
#pragma unroll
                for (int fp = 0; fp < 4; fp++) {
                    uint32_t v0, v1, v2, v3;
                    ldmx4t(v0, v1, v2, v3,
                           s2u(Vt + (ks * 16 + vrow) * AALD + fp * 16 + vc8));
                    mma16816(ofr[2 * fp][0], ofr[2 * fp][1], ofr[2 * fp][2], ofr[2 * fp][3],
                             a0, a1, a2, a3, v0, v1);
                    mma16816(ofr[2 * fp + 1][0], ofr[2 * fp + 1][1], ofr[2 * fp + 1][2], ofr[2 * fp + 1][3],
                             a0, a1, a2, a3, v2, v3);
                }
            }
        }
    }

    l0 += __shfl_xor_sync(0xffffffffu, l0, 1);
    l0 += __shfl_xor_sync(0xffffffffu, l0, 2);
    l1 += __shfl_xor_sync(0xffffffffu, l1, 1);
    l1 += __shfl_xor_sync(0xffffffffu, l1, 2);
    float inv0 = 1.f / l0, inv1 = 1.f / l1;

    const int b = bh >> 4, h = bh & 15;
    int row0 = q0 + warp * 16 + (lane >> 2);
    int colb = h * DK + 2 * (lane & 3);
#pragma unroll
    for (int f = 0; f < 8; f++) {
        *(__nv_bfloat162*)(g_ctxb + (size_t)(b * SEQ + row0) * DMODEL + colb + f * 8) =
            __float22bfloat162_rn(make_float2(ofr[f][0] * inv0, ofr[f][1] * inv0));
        *(__nv_bfloat162*)(g_ctxb + (size_t)(b * SEQ + row0 + 8) * DMODEL + colb + f * 8) =
            __float22bfloat162_rn(make_float2(ofr[f][2] * inv1, ofr[f][3] * inv1));
    }
}

// ---------------- residual + LayerNorm ---------------------------------------
__global__ void __launch_bounds__(256)
ln_kernel(const float* __restrict__ residual, const float* __restrict__ gamma,
          const float* __restrict__ beta, float* __restrict__ out) {
    const int row = blockIdx.x;
    const int t = threadIdx.x;
    const size_t base = (size_t)row * DMODEL + t * 4;

    float4 r4 = *(const float4*)(residual + base);
    float4 p4 = *(const float4*)(g_proj + base);
    float x0 = r4.x + p4.x, x1 = r4.y + p4.y, x2 = r4.z + p4.z, x3 = r4.w + p4.w;

    float s = x0 + x1 + x2 + x3;
    float ss = x0 * x0 + x1 * x1 + x2 * x2 + x3 * x3;
#pragma unroll
    for (int off = 16; off > 0; off >>= 1) {
        s += __shfl_xor_sync(0xffffffffu, s, off);
        ss += __shfl_xor_sync(0xffffffffu, ss, off);
    }
    __shared__ float rs[8], rss[8], stat[2];
    int w = t >> 5, lane = t & 31;
    if (lane == 0) { rs[w] = s; rss[w] = ss; }
    __syncthreads();
    if (t == 0) {
        float S = 0.f, SS = 0.f;
#pragma unroll
        for (int i = 0; i < 8; i++) { S += rs[i]; SS += rss[i]; }
        float mean = S * (1.f / DMODEL);
        float var = SS * (1.f / DMODEL) - mean * mean;
        stat[0] = mean;
        stat[1] = rsqrtf(var + 1e-5f);
    }
    __syncthreads();
    float mean = stat[0], inv = stat[1];

    float4 g4 = *(const float4*)(gamma + t * 4);
    float4 b4 = *(const float4*)(beta + t * 4);
    float4 y;
    y.x = (x0 - mean) * inv * g4.x + b4.x;
    y.y = (x1 - mean) * inv * g4.y + b4.y;
    y.z = (x2 - mean) * inv * g4.z + b4.z;
    y.w = (x3 - mean) * inv * g4.w + b4.w;
    *(float4*)(out + base) = y;
}

// ---------------- launch ------------------------------------------------------
extern "C" void kernel_launch(void* const* d_in, const int* in_sizes, int n_in,
                              void* d_out, int out_size) {
    const float* query = (const float*)d_in[0];
    const float* key   = (const float*)d_in[1];
    const float* value = (const float*)d_in[2];
    const float* Wq    = (const float*)d_in[3];
    const float* bq    = (const float*)d_in[4];
    const float* Wk    = (const float*)d_in[5];
    const float* bk    = (const float*)d_in[6];
    const float* Wv    = (const float*)d_in[7];
    const float* bv    = (const float*)d_in[8];
    const float* Wo    = (const float*)d_in[9];
    const float* bo    = (const float*)d_in[10];
    const float* gamma = (const float*)d_in[11];
    const float* beta  = (const float*)d_in[12];
    float* out = (float*)d_out;

    static bool attr_done = false;
    if (!attr_done) {
        (void)cudaFuncSetAttribute(gemm_qkv,
                                   cudaFuncAttributeMaxDynamicSharedMemorySize, GEMM_SMEM);
        (void)cudaFuncSetAttribute(gemm_o,
                                   cudaFuncAttributeMaxDynamicSharedMemorySize, GEMM_SMEM);
        (void)cudaFuncSetAttribute(attn_kernel,
                                   cudaFuncAttributeMaxDynamicSharedMemorySize, ATTN_SMEM);
        attr_done = true;
    }

    f2b_all<<<(CONV_TOTAL + 255) / 256, 256>>>(query, key, value, Wq, Wk, Wv, Wo);

    dim3 gq(DMODEL / GBN, MTOT / GBM, 3);   // (8, 64, 3)
    gemm_qkv<<<gq, 128, GEMM_SMEM>>>(bq, bk, bv);

    dim3 agrid(SEQ / AQT, BATCH * NHEADS);  // (16, 64)
    attn_kernel<<<agrid, 256, ATTN_SMEM>>>();

    dim3 go(DMODEL / GBN, MTOT / GBM);      // (8, 64)
    gemm_o<<<go, 128, GEMM_SMEM>>>(bo);

    ln_kernel<<<MTOT, 256>>>(query, gamma, beta, out);
}